// round 1
// baseline (speedup 1.0000x reference)
#include <cuda_runtime.h>
#include <math.h>

// Problem constants
#define S_LEN 2048
#define EDIM  1024
#define NH    8
#define DH    128
#define BM    64
#define BN    64

// Scratch (device globals: no allocations allowed)
__device__ float g_ig  [NH * S_LEN];
__device__ float g_logf[NH * S_LEN];
__device__ float g_cum [NH * (S_LEN + 1)];
__device__ float g_h   [S_LEN * EDIM];

// ---------------------------------------------------------------------------
// Kernel 1: gate projections. ig/fg = [q|k|v] @ W.T + b  for all (s, h).
// grid 512 (4 rows/block), 256 threads.
// ---------------------------------------------------------------------------
__global__ void gates_kernel(const float* __restrict__ q,
                             const float* __restrict__ k,
                             const float* __restrict__ v,
                             const float* __restrict__ Wi,
                             const float* __restrict__ bi,
                             const float* __restrict__ Wf,
                             const float* __restrict__ bf) {
    const int b = blockIdx.x;       // 4 rows per block
    const int tid = threadIdx.x;    // 256

    float acc[64];
#pragma unroll
    for (int i = 0; i < 64; i++) acc[i] = 0.f;

#pragma unroll 1
    for (int it = 0; it < 12; it++) {
        const int j = it * 256 + tid;     // 0..3071
        float wi[8], wf[8];
#pragma unroll
        for (int h = 0; h < 8; h++) {
            wi[h] = Wi[h * 3072 + j];
            wf[h] = Wf[h * 3072 + j];
        }
#pragma unroll
        for (int r = 0; r < 4; r++) {
            const int s = b * 4 + r;
            float x;
            if (j < 1024)       x = q[s * 1024 + j];
            else if (j < 2048)  x = k[s * 1024 + (j - 1024)];
            else                x = v[s * 1024 + (j - 2048)];
#pragma unroll
            for (int h = 0; h < 8; h++) {
                acc[r * 16 + h]     = fmaf(x, wi[h], acc[r * 16 + h]);
                acc[r * 16 + 8 + h] = fmaf(x, wf[h], acc[r * 16 + 8 + h]);
            }
        }
    }

    // reduce over 256 threads: warp shfl, then smem across warps
#pragma unroll
    for (int i = 0; i < 64; i++) {
#pragma unroll
        for (int off = 16; off > 0; off >>= 1)
            acc[i] += __shfl_xor_sync(0xffffffffu, acc[i], off);
    }
    __shared__ float red[8][64];
    const int warp = tid >> 5, lane = tid & 31;
    if (lane == 0) {
#pragma unroll
        for (int i = 0; i < 64; i++) red[warp][i] = acc[i];
    }
    __syncthreads();
    if (tid < 64) {
        float vsum = 0.f;
#pragma unroll
        for (int w = 0; w < 8; w++) vsum += red[w][tid];
        const int r = tid >> 4;
        const int o = tid & 15;
        const int h = o & 7;
        const int s = b * 4 + r;
        if (o < 8) {
            g_ig[h * S_LEN + s] = vsum + bi[h];
        } else {
            const float fg = vsum + bf[h];
            // log_sigmoid(x) = min(x,0) - log1p(exp(-|x|))
            g_logf[h * S_LEN + s] = fminf(fg, 0.f) - log1pf(expf(-fabsf(fg)));
        }
    }
}

// ---------------------------------------------------------------------------
// Kernel 2: per-head inclusive scan of log_f (in double for accuracy).
// cum[h][0]=0, cum[h][i] = sum_{j<i} logf[h][j].  grid 8, 1024 threads.
// ---------------------------------------------------------------------------
__global__ void scan_kernel() {
    const int h = blockIdx.x;
    const int tid = threadIdx.x;          // 0..1023, 2 elems each
    const int lane = tid & 31, warp = tid >> 5;

    const double x0 = (double)g_logf[h * S_LEN + 2 * tid];
    const double x1 = (double)g_logf[h * S_LEN + 2 * tid + 1];
    const double s = x0 + x1;

    double inc = s;
#pragma unroll
    for (int off = 1; off < 32; off <<= 1) {
        double u = __shfl_up_sync(0xffffffffu, inc, off);
        if (lane >= off) inc += u;
    }
    __shared__ double wsum[32];
    if (lane == 31) wsum[warp] = inc;
    __syncthreads();
    if (warp == 0) {
        double w = wsum[lane];
#pragma unroll
        for (int off = 1; off < 32; off <<= 1) {
            double u = __shfl_up_sync(0xffffffffu, w, off);
            if (lane >= off) w += u;
        }
        wsum[lane] = w;
    }
    __syncthreads();
    const double base = (warp > 0) ? wsum[warp - 1] : 0.0;
    const double incl = base + inc;
    const double excl = incl - s;

    float* cum = g_cum + h * (S_LEN + 1);
    cum[2 * tid + 1] = (float)(excl + x0);
    cum[2 * tid + 2] = (float)incl;
    if (tid == 0) cum[0] = 0.f;
}

// ---------------------------------------------------------------------------
// Kernel 3: main flash-style mLSTM attention.
// grid 256 = (32 qtiles x 8 heads), 256 threads, 4x4 micro-tiles.
// ---------------------------------------------------------------------------
#define QS_OFF 0
#define KS_OFF (128 * 68)
#define VS_OFF (KS_OFF + 128 * 68)
#define PS_OFF (VS_OFF + 64 * 128)
#define KB_OFF (PS_OFF + 64 * 68)
#define SMEM_FLOATS (KB_OFF + 64)
#define SMEM_BYTES (SMEM_FLOATS * 4)

extern "C" __global__ void __launch_bounds__(256, 1)
mlstm_main_kernel(const float* __restrict__ q,
                  const float* __restrict__ k,
                  const float* __restrict__ v) {
    extern __shared__ float sm[];
    float* Qs = sm + QS_OFF;   // [128][68] transposed (dim-major), padded
    float* Ks = sm + KS_OFF;   // [128][68]
    float* Vs = sm + VS_OFF;   // [64][128]
    float* Ps = sm + PS_OFF;   // [64][68]  Ps[key][row]
    float* kB = sm + KB_OFF;   // [64]      B[c] = ig[t] - cum[t+1]

    const int bx = blockIdx.x;
    const int qi = 31 - (bx >> 3);       // longest-work-first
    const int h  = bx & 7;
    const int tid = threadIdx.x;
    const int tx = tid & 15;             // 16 col-groups
    const int ty = tid >> 4;             // 16 row-groups

    const float scale = 0.08838834764831845f;  // 1/sqrt(128)

    // Load Q tile transposed: Qs[kk][r]
    for (int idx = tid; idx < BM * DH; idx += 256) {
        const int r = idx >> 7, kk = idx & 127;
        Qs[kk * 68 + r] = q[(qi * BM + r) * EDIM + h * DH + kk];
    }

    float cumq[4];
    int srow[4];
#pragma unroll
    for (int i = 0; i < 4; i++) {
        srow[i] = qi * BM + ty * 4 + i;
        cumq[i] = g_cum[h * (S_LEN + 1) + srow[i] + 1];
    }

    float m[4], l[4], o[4][8];
#pragma unroll
    for (int i = 0; i < 4; i++) {
        m[i] = -INFINITY; l[i] = 0.f;
#pragma unroll
        for (int d = 0; d < 8; d++) o[i][d] = 0.f;
    }

    for (int kt = 0; kt <= qi; kt++) {
        __syncthreads();   // prev PV done (and first-iter Q stores ordered)
        const int t0 = kt * BN;
        for (int idx = tid; idx < BN * DH; idx += 256) {
            const int r = idx >> 7, kk = idx & 127;
            Ks[kk * 68 + r] = k[(t0 + r) * EDIM + h * DH + kk];
        }
        for (int idx = tid; idx < BN * DH; idx += 256) {
            const int r = idx >> 7, d = idx & 127;
            Vs[r * 128 + d] = v[(t0 + r) * EDIM + h * DH + d];
        }
        if (tid < 64) {
            const int t = t0 + tid;
            kB[tid] = g_ig[h * S_LEN + t] - g_cum[h * (S_LEN + 1) + t + 1];
        }
        __syncthreads();

        // ---- QK^T 64x64x128 micro-GEMM ----
        float acc[4][4];
#pragma unroll
        for (int i = 0; i < 4; i++)
#pragma unroll
            for (int j = 0; j < 4; j++) acc[i][j] = 0.f;

#pragma unroll 16
        for (int kk = 0; kk < 128; kk++) {
            const float4 a4 = *(const float4*)(Qs + kk * 68 + ty * 4);
            const float4 b4 = *(const float4*)(Ks + kk * 68 + tx * 4);
            const float av[4] = {a4.x, a4.y, a4.z, a4.w};
            const float bv[4] = {b4.x, b4.y, b4.z, b4.w};
#pragma unroll
            for (int i = 0; i < 4; i++)
#pragma unroll
                for (int j = 0; j < 4; j++)
                    acc[i][j] = fmaf(av[i], bv[j], acc[i][j]);
        }

        // ---- gate math ----
        const int c0 = tx * 4;
        float Bc[4];
#pragma unroll
        for (int j = 0; j < 4; j++) Bc[j] = kB[c0 + j];

        // masked per-row max of B over this tile, reduced across the 16 tx
        float rowB[4];
#pragma unroll
        for (int i = 0; i < 4; i++) {
            float rb = -INFINITY;
#pragma unroll
            for (int j = 0; j < 4; j++) {
                const int t = t0 + c0 + j;
                if (t <= srow[i]) rb = fmaxf(rb, Bc[j]);
            }
            rowB[i] = rb;
        }
#pragma unroll
        for (int i = 0; i < 4; i++) {
#pragma unroll
            for (int off = 1; off < 16; off <<= 1)
                rowB[i] = fmaxf(rowB[i], __shfl_xor_sync(0xffffffffu, rowB[i], off, 16));
        }

        // chunk (16-key) max of B, unmasked — bounds exp arguments
        float cb = fmaxf(fmaxf(Bc[0], Bc[1]), fmaxf(Bc[2], Bc[3]));
        cb = fmaxf(cb, __shfl_xor_sync(0xffffffffu, cb, 1, 4));
        cb = fmaxf(cb, __shfl_xor_sync(0xffffffffu, cb, 2, 4));

        float eB[4];
#pragma unroll
        for (int j = 0; j < 4; j++) eB[j] = __expf(Bc[j] - cb);

        float P[4][4], fs[4], tl[4];
#pragma unroll
        for (int i = 0; i < 4; i++) {
            const float mn = fmaxf(m[i], cumq[i] + rowB[i]);
            fs[i] = __expf(m[i] - mn);
            m[i] = mn;
            const float eA = __expf(cumq[i] - mn + cb);
            float rs = 0.f;
#pragma unroll
            for (int j = 0; j < 4; j++) {
                const int t = t0 + c0 + j;
                const float p = (t <= srow[i]) ? acc[i][j] * scale * eA * eB[j] : 0.f;
                P[i][j] = p;
                rs += p;
            }
            tl[i] = rs;
        }
#pragma unroll
        for (int i = 0; i < 4; i++) {
#pragma unroll
            for (int off = 1; off < 16; off <<= 1)
                tl[i] += __shfl_xor_sync(0xffffffffu, tl[i], off, 16);
            l[i] = l[i] * fs[i] + tl[i];
#pragma unroll
            for (int d = 0; d < 8; d++) o[i][d] *= fs[i];
        }

        // stage P to smem: Ps[key][row]
#pragma unroll
        for (int j = 0; j < 4; j++) {
            float4 pv = make_float4(P[0][j], P[1][j], P[2][j], P[3][j]);
            *(float4*)(Ps + (c0 + j) * 68 + ty * 4) = pv;
        }
        __syncthreads();

        // ---- P @ V: o[4 rows][8 dims] ----
#pragma unroll 8
        for (int tt = 0; tt < 64; tt++) {
            const float4 p4 = *(const float4*)(Ps + tt * 68 + ty * 4);
            const float4 va = *(const float4*)(Vs + tt * 128 + tx * 8);
            const float4 vb = *(const float4*)(Vs + tt * 128 + tx * 8 + 4);
            const float pa[4] = {p4.x, p4.y, p4.z, p4.w};
            const float vv[8] = {va.x, va.y, va.z, va.w, vb.x, vb.y, vb.z, vb.w};
#pragma unroll
            for (int i = 0; i < 4; i++)
#pragma unroll
                for (int d = 0; d < 8; d++)
                    o[i][d] = fmaf(pa[i], vv[d], o[i][d]);
        }
    }

    // epilogue: normalizer = max(|l|, exp(-m)); h = o / (norm + eps)
#pragma unroll
    for (int i = 0; i < 4; i++) {
        const float norm = fmaxf(fabsf(l[i]), __expf(-m[i])) + 1e-6f;
        const float inv = 1.f / norm;
        float* dst = g_h + srow[i] * EDIM + h * DH + tx * 8;
        float4 oa = make_float4(o[i][0] * inv, o[i][1] * inv, o[i][2] * inv, o[i][3] * inv);
        float4 ob = make_float4(o[i][4] * inv, o[i][5] * inv, o[i][6] * inv, o[i][7] * inv);
        *(float4*)(dst)     = oa;
        *(float4*)(dst + 4) = ob;
    }
}

// ---------------------------------------------------------------------------
// Kernel 4: residual layer norm.  out = LN(h) * (1 + w).  grid 2048, 256 thr.
// ---------------------------------------------------------------------------
__global__ void ln_kernel(const float* __restrict__ lnw, float* __restrict__ out) {
    const int s = blockIdx.x;
    const int tid = threadIdx.x;
    const int lane = tid & 31, warp = tid >> 5;

    const float4 x = *(const float4*)(g_h + s * EDIM + tid * 4);

    __shared__ float wsum[8];
    __shared__ float stat[2];

    float lsum = x.x + x.y + x.z + x.w;
#pragma unroll
    for (int off = 16; off > 0; off >>= 1)
        lsum += __shfl_xor_sync(0xffffffffu, lsum, off);
    if (lane == 0) wsum[warp] = lsum;
    __syncthreads();
    if (tid == 0) {
        float t = 0.f;
#pragma unroll
        for (int w = 0; w < 8; w++) t += wsum[w];
        stat[0] = t * (1.f / 1024.f);
    }
    __syncthreads();
    const float mean = stat[0];

    const float d0 = x.x - mean, d1 = x.y - mean, d2 = x.z - mean, d3 = x.w - mean;
    float lsq = d0 * d0 + d1 * d1 + d2 * d2 + d3 * d3;
#pragma unroll
    for (int off = 16; off > 0; off >>= 1)
        lsq += __shfl_xor_sync(0xffffffffu, lsq, off);
    if (lane == 0) wsum[warp] = lsq;
    __syncthreads();
    if (tid == 0) {
        float t = 0.f;
#pragma unroll
        for (int w = 0; w < 8; w++) t += wsum[w];
        stat[1] = rsqrtf(t * (1.f / 1024.f) + 1e-5f);
    }
    __syncthreads();
    const float rstd = stat[1];

    const float4 w4 = *(const float4*)(lnw + tid * 4);
    float4 r;
    r.x = d0 * rstd * (1.f + w4.x);
    r.y = d1 * rstd * (1.f + w4.y);
    r.z = d2 * rstd * (1.f + w4.z);
    r.w = d3 * rstd * (1.f + w4.w);
    *(float4*)(out + s * EDIM + tid * 4) = r;
}

// ---------------------------------------------------------------------------
extern "C" void kernel_launch(void* const* d_in, const int* in_sizes, int n_in,
                              void* d_out, int out_size) {
    const float* q   = (const float*)d_in[0];
    const float* k   = (const float*)d_in[1];
    const float* v   = (const float*)d_in[2];
    const float* Wi  = (const float*)d_in[3];
    const float* bi  = (const float*)d_in[4];
    const float* Wf  = (const float*)d_in[5];
    const float* bf  = (const float*)d_in[6];
    const float* lnw = (const float*)d_in[7];
    float* out = (float*)d_out;

    gates_kernel<<<S_LEN / 4, 256>>>(q, k, v, Wi, bi, Wf, bf);
    scan_kernel<<<NH, 1024>>>();

    cudaFuncSetAttribute(mlstm_main_kernel,
                         cudaFuncAttributeMaxDynamicSharedMemorySize, SMEM_BYTES);
    mlstm_main_kernel<<<32 * NH, 256, SMEM_BYTES>>>(q, k, v);

    ln_kernel<<<S_LEN, 256>>>(lnw, out);
}

// round 2
// speedup vs baseline: 1.0091x; 1.0091x over previous
#include <cuda_runtime.h>
#include <math.h>

// Problem constants
#define S_LEN 2048
#define EDIM  1024
#define NH    8
#define DH    128
#define BM    64
#define BN    64

typedef unsigned long long ull;

// ---- packed f32x2 helpers (Blackwell FFMA2 — PTX-only path) ----
__device__ __forceinline__ ull ffma2(ull a, ull b, ull c) {
    ull d;
    asm("fma.rn.f32x2 %0, %1, %2, %3;" : "=l"(d) : "l"(a), "l"(b), "l"(c));
    return d;
}
__device__ __forceinline__ ull fmul2(ull a, ull b) {
    ull d;
    asm("mul.rn.f32x2 %0, %1, %2;" : "=l"(d) : "l"(a), "l"(b));
    return d;
}
__device__ __forceinline__ ull dup2f(float x) {
    ull d;
    asm("mov.b64 %0, {%1, %1};" : "=l"(d) : "f"(x));
    return d;
}
__device__ __forceinline__ void unpk2(ull v, float& lo, float& hi) {
    asm("mov.b64 {%0, %1}, %2;" : "=f"(lo), "=f"(hi) : "l"(v));
}

// Scratch (device globals: no allocations allowed)
__device__ float g_ig  [NH * S_LEN];
__device__ float g_logf[NH * S_LEN];
__device__ float g_cum [NH * (S_LEN + 1)];
__device__ float g_h   [S_LEN * EDIM];

// ---------------------------------------------------------------------------
// Kernel 1: gate projections. ig/fg = [q|k|v] @ W.T + b  for all (s, h).
// grid 512 (4 rows/block), 256 threads.
// ---------------------------------------------------------------------------
__global__ void gates_kernel(const float* __restrict__ q,
                             const float* __restrict__ k,
                             const float* __restrict__ v,
                             const float* __restrict__ Wi,
                             const float* __restrict__ bi,
                             const float* __restrict__ Wf,
                             const float* __restrict__ bf) {
    const int b = blockIdx.x;       // 4 rows per block
    const int tid = threadIdx.x;    // 256

    float acc[64];
#pragma unroll
    for (int i = 0; i < 64; i++) acc[i] = 0.f;

#pragma unroll 1
    for (int it = 0; it < 12; it++) {
        const int j = it * 256 + tid;     // 0..3071
        float wi[8], wf[8];
#pragma unroll
        for (int h = 0; h < 8; h++) {
            wi[h] = Wi[h * 3072 + j];
            wf[h] = Wf[h * 3072 + j];
        }
#pragma unroll
        for (int r = 0; r < 4; r++) {
            const int s = b * 4 + r;
            float x;
            if (j < 1024)       x = q[s * 1024 + j];
            else if (j < 2048)  x = k[s * 1024 + (j - 1024)];
            else                x = v[s * 1024 + (j - 2048)];
#pragma unroll
            for (int h = 0; h < 8; h++) {
                acc[r * 16 + h]     = fmaf(x, wi[h], acc[r * 16 + h]);
                acc[r * 16 + 8 + h] = fmaf(x, wf[h], acc[r * 16 + 8 + h]);
            }
        }
    }

    // reduce over 256 threads: warp shfl, then smem across warps
#pragma unroll
    for (int i = 0; i < 64; i++) {
#pragma unroll
        for (int off = 16; off > 0; off >>= 1)
            acc[i] += __shfl_xor_sync(0xffffffffu, acc[i], off);
    }
    __shared__ float red[8][64];
    const int warp = tid >> 5, lane = tid & 31;
    if (lane == 0) {
#pragma unroll
        for (int i = 0; i < 64; i++) red[warp][i] = acc[i];
    }
    __syncthreads();
    if (tid < 64) {
        float vsum = 0.f;
#pragma unroll
        for (int w = 0; w < 8; w++) vsum += red[w][tid];
        const int r = tid >> 4;
        const int o = tid & 15;
        const int h = o & 7;
        const int s = b * 4 + r;
        if (o < 8) {
            g_ig[h * S_LEN + s] = vsum + bi[h];
        } else {
            const float fg = vsum + bf[h];
            // log_sigmoid(x) = min(x,0) - log1p(exp(-|x|))
            g_logf[h * S_LEN + s] = fminf(fg, 0.f) - log1pf(expf(-fabsf(fg)));
        }
    }
}

// ---------------------------------------------------------------------------
// Kernel 2: per-head inclusive scan of log_f (in double for accuracy).
// cum[h][0]=0, cum[h][i] = sum_{j<i} logf[h][j].  grid 8, 1024 threads.
// ---------------------------------------------------------------------------
__global__ void scan_kernel() {
    const int h = blockIdx.x;
    const int tid = threadIdx.x;          // 0..1023, 2 elems each
    const int lane = tid & 31, warp = tid >> 5;

    const double x0 = (double)g_logf[h * S_LEN + 2 * tid];
    const double x1 = (double)g_logf[h * S_LEN + 2 * tid + 1];
    const double s = x0 + x1;

    double inc = s;
#pragma unroll
    for (int off = 1; off < 32; off <<= 1) {
        double u = __shfl_up_sync(0xffffffffu, inc, off);
        if (lane >= off) inc += u;
    }
    __shared__ double wsum[32];
    if (lane == 31) wsum[warp] = inc;
    __syncthreads();
    if (warp == 0) {
        double w = wsum[lane];
#pragma unroll
        for (int off = 1; off < 32; off <<= 1) {
            double u = __shfl_up_sync(0xffffffffu, w, off);
            if (lane >= off) w += u;
        }
        wsum[lane] = w;
    }
    __syncthreads();
    const double base = (warp > 0) ? wsum[warp - 1] : 0.0;
    const double incl = base + inc;
    const double excl = incl - s;

    float* cum = g_cum + h * (S_LEN + 1);
    cum[2 * tid + 1] = (float)(excl + x0);
    cum[2 * tid + 2] = (float)incl;
    if (tid == 0) cum[0] = 0.f;
}

// ---------------------------------------------------------------------------
// Kernel 3: main flash-style mLSTM attention with packed f32x2 FMA.
// grid 256 = (32 qtiles x 8 heads), 256 threads, 4x4 micro-tiles.
// ---------------------------------------------------------------------------
#define QS_OFF 0
#define KS_OFF (128 * 68)
#define VS_OFF (KS_OFF + 128 * 68)
#define PS_OFF (VS_OFF + 64 * 128)
#define KB_OFF (PS_OFF + 64 * 68)
#define SMEM_FLOATS (KB_OFF + 64)
#define SMEM_BYTES (SMEM_FLOATS * 4)

extern "C" __global__ void __launch_bounds__(256, 1)
mlstm_main_kernel(const float* __restrict__ q,
                  const float* __restrict__ k,
                  const float* __restrict__ v) {
    extern __shared__ float sm[];
    float* Qs = sm + QS_OFF;   // [128][68] transposed (dim-major), padded
    float* Ks = sm + KS_OFF;   // [128][68]
    float* Vs = sm + VS_OFF;   // [64][128]
    float* Ps = sm + PS_OFF;   // [64][68]  Ps[key][row]
    float* kB = sm + KB_OFF;   // [64]      B[c] = ig[t] - cum[t+1]

    const int bx = blockIdx.x;
    const int qi = 31 - (bx >> 3);       // longest-work-first
    const int h  = bx & 7;
    const int tid = threadIdx.x;
    const int tx = tid & 15;             // 16 col-groups
    const int ty = tid >> 4;             // 16 row-groups

    const float scale = 0.08838834764831845f;  // 1/sqrt(128)

    // Load Q tile transposed: Qs[kk][r], scale folded in
    for (int idx = tid; idx < BM * DH; idx += 256) {
        const int r = idx >> 7, kk = idx & 127;
        Qs[kk * 68 + r] = q[(qi * BM + r) * EDIM + h * DH + kk] * scale;
    }

    float cumq[4];
    int srow[4];
#pragma unroll
    for (int i = 0; i < 4; i++) {
        srow[i] = qi * BM + ty * 4 + i;
        cumq[i] = g_cum[h * (S_LEN + 1) + srow[i] + 1];
    }

    float m[4], l[4];
    ull o2[4][4];
#pragma unroll
    for (int i = 0; i < 4; i++) {
        m[i] = -INFINITY; l[i] = 0.f;
#pragma unroll
        for (int d = 0; d < 4; d++) o2[i][d] = 0ull;
    }

    for (int kt = 0; kt <= qi; kt++) {
        __syncthreads();   // prev PV done (and first-iter Q stores ordered)
        const int t0 = kt * BN;
        for (int idx = tid; idx < BN * DH; idx += 256) {
            const int r = idx >> 7, kk = idx & 127;
            Ks[kk * 68 + r] = k[(t0 + r) * EDIM + h * DH + kk];
        }
        for (int idx = tid; idx < BN * DH; idx += 256) {
            const int r = idx >> 7, d = idx & 127;
            Vs[r * 128 + d] = v[(t0 + r) * EDIM + h * DH + d];
        }
        if (tid < 64) {
            const int t = t0 + tid;
            kB[tid] = g_ig[h * S_LEN + t] - g_cum[h * (S_LEN + 1) + t + 1];
        }
        __syncthreads();

        // ---- QK^T 64x64x128 micro-GEMM (packed f32x2) ----
        ull acc2[4][2];
#pragma unroll
        for (int i = 0; i < 4; i++) { acc2[i][0] = 0ull; acc2[i][1] = 0ull; }

#pragma unroll 16
        for (int kk = 0; kk < 128; kk++) {
            const float4 a4 = *(const float4*)(Qs + kk * 68 + ty * 4);
            const ulonglong2 b2 = *(const ulonglong2*)(Ks + kk * 68 + tx * 4);
            const float av[4] = {a4.x, a4.y, a4.z, a4.w};
#pragma unroll
            for (int i = 0; i < 4; i++) {
                const ull ad = dup2f(av[i]);
                acc2[i][0] = ffma2(ad, b2.x, acc2[i][0]);
                acc2[i][1] = ffma2(ad, b2.y, acc2[i][1]);
            }
        }

        float acc[4][4];
#pragma unroll
        for (int i = 0; i < 4; i++) {
            unpk2(acc2[i][0], acc[i][0], acc[i][1]);
            unpk2(acc2[i][1], acc[i][2], acc[i][3]);
        }

        // ---- gate math ----
        const int c0 = tx * 4;
        float Bc[4];
#pragma unroll
        for (int j = 0; j < 4; j++) Bc[j] = kB[c0 + j];

        // masked per-row max of B over this tile, reduced across the 16 tx
        float rowB[4];
#pragma unroll
        for (int i = 0; i < 4; i++) {
            float rb = -INFINITY;
#pragma unroll
            for (int j = 0; j < 4; j++) {
                const int t = t0 + c0 + j;
                if (t <= srow[i]) rb = fmaxf(rb, Bc[j]);
            }
            rowB[i] = rb;
        }
#pragma unroll
        for (int i = 0; i < 4; i++) {
#pragma unroll
            for (int off = 1; off < 16; off <<= 1)
                rowB[i] = fmaxf(rowB[i], __shfl_xor_sync(0xffffffffu, rowB[i], off, 16));
        }

        // chunk (16-key) max of B, unmasked — bounds exp arguments
        float cb = fmaxf(fmaxf(Bc[0], Bc[1]), fmaxf(Bc[2], Bc[3]));
        cb = fmaxf(cb, __shfl_xor_sync(0xffffffffu, cb, 1, 4));
        cb = fmaxf(cb, __shfl_xor_sync(0xffffffffu, cb, 2, 4));

        float eB[4];
#pragma unroll
        for (int j = 0; j < 4; j++) eB[j] = __expf(Bc[j] - cb);

        float P[4][4], fs[4], tl[4];
#pragma unroll
        for (int i = 0; i < 4; i++) {
            const float mn = fmaxf(m[i], cumq[i] + rowB[i]);
            fs[i] = __expf(m[i] - mn);
            m[i] = mn;
            const float eA = __expf(cumq[i] - mn + cb);
            float rs = 0.f;
#pragma unroll
            for (int j = 0; j < 4; j++) {
                const int t = t0 + c0 + j;
                const float p = (t <= srow[i]) ? acc[i][j] * eA * eB[j] : 0.f;
                P[i][j] = p;
                rs += p;
            }
            tl[i] = rs;
        }
#pragma unroll
        for (int i = 0; i < 4; i++) {
#pragma unroll
            for (int off = 1; off < 16; off <<= 1)
                tl[i] += __shfl_xor_sync(0xffffffffu, tl[i], off, 16);
            l[i] = l[i] * fs[i] + tl[i];
            const ull fsd = dup2f(fs[i]);
#pragma unroll
            for (int d = 0; d < 4; d++) o2[i][d] = fmul2(o2[i][d], fsd);
        }

        // stage P to smem: Ps[key][row]
#pragma unroll
        for (int j = 0; j < 4; j++) {
            float4 pv = make_float4(P[0][j], P[1][j], P[2][j], P[3][j]);
            *(float4*)(Ps + (c0 + j) * 68 + ty * 4) = pv;
        }
        __syncthreads();

        // ---- P @ V: o[4 rows][8 dims] (packed f32x2) ----
#pragma unroll 8
        for (int tt = 0; tt < 64; tt++) {
            const float4 p4 = *(const float4*)(Ps + tt * 68 + ty * 4);
            const ulonglong2 va = *(const ulonglong2*)(Vs + tt * 128 + tx * 8);
            const ulonglong2 vb = *(const ulonglong2*)(Vs + tt * 128 + tx * 8 + 4);
            const float pa[4] = {p4.x, p4.y, p4.z, p4.w};
#pragma unroll
            for (int i = 0; i < 4; i++) {
                const ull pd = dup2f(pa[i]);
                o2[i][0] = ffma2(pd, va.x, o2[i][0]);
                o2[i][1] = ffma2(pd, va.y, o2[i][1]);
                o2[i][2] = ffma2(pd, vb.x, o2[i][2]);
                o2[i][3] = ffma2(pd, vb.y, o2[i][3]);
            }
        }
    }

    // epilogue: normalizer = max(|l|, exp(-m)); h = o / (norm + eps)
#pragma unroll
    for (int i = 0; i < 4; i++) {
        const float norm = fmaxf(fabsf(l[i]), __expf(-m[i])) + 1e-6f;
        const ull iv = dup2f(1.f / norm);
        float* dst = g_h + srow[i] * EDIM + h * DH + tx * 8;
        ulonglong2 ra, rb;
        ra.x = fmul2(o2[i][0], iv); ra.y = fmul2(o2[i][1], iv);
        rb.x = fmul2(o2[i][2], iv); rb.y = fmul2(o2[i][3], iv);
        *(ulonglong2*)(dst)     = ra;
        *(ulonglong2*)(dst + 4) = rb;
    }
}

// ---------------------------------------------------------------------------
// Kernel 4: residual layer norm.  out = LN(h) * (1 + w).  grid 2048, 256 thr.
// ---------------------------------------------------------------------------
__global__ void ln_kernel(const float* __restrict__ lnw, float* __restrict__ out) {
    const int s = blockIdx.x;
    const int tid = threadIdx.x;
    const int lane = tid & 31, warp = tid >> 5;

    const float4 x = *(const float4*)(g_h + s * EDIM + tid * 4);

    __shared__ float wsum[8];
    __shared__ float stat[2];

    float lsum = x.x + x.y + x.z + x.w;
#pragma unroll
    for (int off = 16; off > 0; off >>= 1)
        lsum += __shfl_xor_sync(0xffffffffu, lsum, off);
    if (lane == 0) wsum[warp] = lsum;
    __syncthreads();
    if (tid == 0) {
        float t = 0.f;
#pragma unroll
        for (int w = 0; w < 8; w++) t += wsum[w];
        stat[0] = t * (1.f / 1024.f);
    }
    __syncthreads();
    const float mean = stat[0];

    const float d0 = x.x - mean, d1 = x.y - mean, d2 = x.z - mean, d3 = x.w - mean;
    float lsq = d0 * d0 + d1 * d1 + d2 * d2 + d3 * d3;
#pragma unroll
    for (int off = 16; off > 0; off >>= 1)
        lsq += __shfl_xor_sync(0xffffffffu, lsq, off);
    if (lane == 0) wsum[warp] = lsq;
    __syncthreads();
    if (tid == 0) {
        float t = 0.f;
#pragma unroll
        for (int w = 0; w < 8; w++) t += wsum[w];
        stat[1] = rsqrtf(t * (1.f / 1024.f) + 1e-5f);
    }
    __syncthreads();
    const float rstd = stat[1];

    const float4 w4 = *(const float4*)(lnw + tid * 4);
    float4 r;
    r.x = d0 * rstd * (1.f + w4.x);
    r.y = d1 * rstd * (1.f + w4.y);
    r.z = d2 * rstd * (1.f + w4.z);
    r.w = d3 * rstd * (1.f + w4.w);
    *(float4*)(out + s * EDIM + tid * 4) = r;
}

// ---------------------------------------------------------------------------
extern "C" void kernel_launch(void* const* d_in, const int* in_sizes, int n_in,
                              void* d_out, int out_size) {
    const float* q   = (const float*)d_in[0];
    const float* k   = (const float*)d_in[1];
    const float* v   = (const float*)d_in[2];
    const float* Wi  = (const float*)d_in[3];
    const float* bi  = (const float*)d_in[4];
    const float* Wf  = (const float*)d_in[5];
    const float* bf  = (const float*)d_in[6];
    const float* lnw = (const float*)d_in[7];
    float* out = (float*)d_out;

    gates_kernel<<<S_LEN / 4, 256>>>(q, k, v, Wi, bi, Wf, bf);
    scan_kernel<<<NH, 1024>>>();

    cudaFuncSetAttribute(mlstm_main_kernel,
                         cudaFuncAttributeMaxDynamicSharedMemorySize, SMEM_BYTES);
    mlstm_main_kernel<<<32 * NH, 256, SMEM_BYTES>>>(q, k, v);

    ln_kernel<<<S_LEN, 256>>>(lnw, out);
}

// round 3
// speedup vs baseline: 1.4693x; 1.4561x over previous
#include <cuda_runtime.h>
#include <math.h>
#include <stdint.h>

// Problem constants
#define S_LEN 2048
#define EDIM  1024
#define NH    8
#define DH    128
#define BM    64
#define BN    64

typedef unsigned long long ull;

// ---- packed f32x2 helpers (Blackwell FFMA2 — PTX-only path) ----
__device__ __forceinline__ ull ffma2(ull a, ull b, ull c) {
    ull d;
    asm("fma.rn.f32x2 %0, %1, %2, %3;" : "=l"(d) : "l"(a), "l"(b), "l"(c));
    return d;
}
__device__ __forceinline__ ull fmul2(ull a, ull b) {
    ull d;
    asm("mul.rn.f32x2 %0, %1, %2;" : "=l"(d) : "l"(a), "l"(b));
    return d;
}
__device__ __forceinline__ ull dup2f(float x) {
    ull d;
    asm("mov.b64 %0, {%1, %1};" : "=l"(d) : "f"(x));
    return d;
}
__device__ __forceinline__ void unpk2(ull v, float& lo, float& hi) {
    asm("mov.b64 {%0, %1}, %2;" : "=f"(lo), "=f"(hi) : "l"(v));
}
__device__ __forceinline__ void cp16(uint32_t dst, const float* src) {
    asm volatile("cp.async.cg.shared.global [%0], [%1], 16;" :: "r"(dst), "l"(src));
}
__device__ __forceinline__ void cp_commit() {
    asm volatile("cp.async.commit_group;");
}
__device__ __forceinline__ void cp_wait0() {
    asm volatile("cp.async.wait_group 0;");
}

// Scratch (device globals: no allocations allowed)
__device__ float g_ig  [NH * S_LEN];
__device__ float g_logf[NH * S_LEN];
__device__ float g_cumS[NH * S_LEN];    // inclusive scan: g_cumS[t] = sum_{j<=t} logf
__device__ float g_h   [S_LEN * EDIM];

// ---------------------------------------------------------------------------
// Kernel 1: gate projections. ig/fg = [q|k|v] @ W.T + b  for all (s, h).
// ---------------------------------------------------------------------------
__global__ void gates_kernel(const float* __restrict__ q,
                             const float* __restrict__ k,
                             const float* __restrict__ v,
                             const float* __restrict__ Wi,
                             const float* __restrict__ bi,
                             const float* __restrict__ Wf,
                             const float* __restrict__ bf) {
    const int b = blockIdx.x;       // 4 rows per block
    const int tid = threadIdx.x;    // 256

    float acc[64];
#pragma unroll
    for (int i = 0; i < 64; i++) acc[i] = 0.f;

#pragma unroll 1
    for (int it = 0; it < 12; it++) {
        const int j = it * 256 + tid;     // 0..3071
        float wi[8], wf[8];
#pragma unroll
        for (int h = 0; h < 8; h++) {
            wi[h] = Wi[h * 3072 + j];
            wf[h] = Wf[h * 3072 + j];
        }
#pragma unroll
        for (int r = 0; r < 4; r++) {
            const int s = b * 4 + r;
            float x;
            if (j < 1024)       x = q[s * 1024 + j];
            else if (j < 2048)  x = k[s * 1024 + (j - 1024)];
            else                x = v[s * 1024 + (j - 2048)];
#pragma unroll
            for (int h = 0; h < 8; h++) {
                acc[r * 16 + h]     = fmaf(x, wi[h], acc[r * 16 + h]);
                acc[r * 16 + 8 + h] = fmaf(x, wf[h], acc[r * 16 + 8 + h]);
            }
        }
    }

#pragma unroll
    for (int i = 0; i < 64; i++) {
#pragma unroll
        for (int off = 16; off > 0; off >>= 1)
            acc[i] += __shfl_xor_sync(0xffffffffu, acc[i], off);
    }
    __shared__ float red[8][64];
    const int warp = tid >> 5, lane = tid & 31;
    if (lane == 0) {
#pragma unroll
        for (int i = 0; i < 64; i++) red[warp][i] = acc[i];
    }
    __syncthreads();
    if (tid < 64) {
        float vsum = 0.f;
#pragma unroll
        for (int w = 0; w < 8; w++) vsum += red[w][tid];
        const int r = tid >> 4;
        const int o = tid & 15;
        const int h = o & 7;
        const int s = b * 4 + r;
        if (o < 8) {
            g_ig[h * S_LEN + s] = vsum + bi[h];
        } else {
            const float fg = vsum + bf[h];
            g_logf[h * S_LEN + s] = fminf(fg, 0.f) - log1pf(expf(-fabsf(fg)));
        }
    }
}

// ---------------------------------------------------------------------------
// Kernel 2: per-head inclusive scan of log_f (double precision).
// ---------------------------------------------------------------------------
__global__ void scan_kernel() {
    const int h = blockIdx.x;
    const int tid = threadIdx.x;          // 0..1023, 2 elems each
    const int lane = tid & 31, warp = tid >> 5;

    const double x0 = (double)g_logf[h * S_LEN + 2 * tid];
    const double x1 = (double)g_logf[h * S_LEN + 2 * tid + 1];
    const double s = x0 + x1;

    double inc = s;
#pragma unroll
    for (int off = 1; off < 32; off <<= 1) {
        double u = __shfl_up_sync(0xffffffffu, inc, off);
        if (lane >= off) inc += u;
    }
    __shared__ double wsum[32];
    if (lane == 31) wsum[warp] = inc;
    __syncthreads();
    if (warp == 0) {
        double w = wsum[lane];
#pragma unroll
        for (int off = 1; off < 32; off <<= 1) {
            double u = __shfl_up_sync(0xffffffffu, w, off);
            if (lane >= off) w += u;
        }
        wsum[lane] = w;
    }
    __syncthreads();
    const double base = (warp > 0) ? wsum[warp - 1] : 0.0;
    const double incl = base + inc;
    const double excl = incl - s;

    float* cum = g_cumS + h * S_LEN;
    cum[2 * tid]     = (float)(excl + x0);
    cum[2 * tid + 1] = (float)incl;
}

// ---------------------------------------------------------------------------
// Kernel 3: main flash-style mLSTM attention. cp.async double-buffered K/V.
// grid 256 = (32 qtiles x 8 heads), 256 threads, 4x4 micro-tiles.
// ---------------------------------------------------------------------------
#define QSTR 132
#define VSTR 132
#define QS_OFF 0
#define KS_OFF (64 * 132)                      // Q: 8448 floats
#define VS_OFF (KS_OFF + 2 * 64 * 128)         // K double buf: 16384
#define PS_OFF (VS_OFF + 2 * 64 * 132)         // V double buf: 16896
#define SMEM_FLOATS (PS_OFF + 64 * 68)         // P: 4352
#define SMEM_BYTES (SMEM_FLOATS * 4)

__device__ __forceinline__ void prefetch_tile(const float* __restrict__ kg,
                                              const float* __restrict__ vg,
                                              float* Ksb, float* Vsb, int tid) {
    uint32_t kbase = (uint32_t)__cvta_generic_to_shared(Ksb);
    uint32_t vbase = (uint32_t)__cvta_generic_to_shared(Vsb);
#pragma unroll
    for (int it = 0; it < 8; it++) {
        const int c = it * 256 + tid;     // 0..2047 chunks of 16B
        const int key = c >> 5, ch = c & 31;
        const int swz = (key ^ (key >> 3)) & 7;
        cp16(kbase + (uint32_t)(key * 128 + ((ch ^ swz) << 2)) * 4u,
             kg + key * EDIM + ch * 4);
        cp16(vbase + (uint32_t)(key * VSTR + (ch << 2)) * 4u,
             vg + key * EDIM + ch * 4);
    }
    cp_commit();
}

extern "C" __global__ void __launch_bounds__(256, 1)
mlstm_main_kernel(const float* __restrict__ q,
                  const float* __restrict__ k,
                  const float* __restrict__ v) {
    extern __shared__ float sm[];
    float* Qs  = sm + QS_OFF;    // [64][132] row-major, scale folded
    float* Ks0 = sm + KS_OFF;    // [64][128] swizzled, double buffered
    float* Vs0 = sm + VS_OFF;    // [64][132] double buffered
    float* Ps  = sm + PS_OFF;    // [64][68]  Ps[key][row]

    const int bx = blockIdx.x;
    const int qi = 31 - (bx >> 3);       // longest-work-first
    const int h  = bx & 7;
    const int tid = threadIdx.x;
    const int tx = tid & 15;             // 16 col-groups (keys)
    const int ty = tid >> 4;             // 16 row-groups (queries)

    const float scale = 0.08838834764831845f;  // 1/sqrt(128)
    const float* kg0 = k + h * DH;
    const float* vg0 = v + h * DH;

    // prefetch tile 0
    prefetch_tile(kg0, vg0, Ks0, Vs0, tid);

    // Load Q tile row-major, scale folded
    const int qrow0 = qi * BM;
    for (int idx = tid; idx < BM * DH; idx += 256) {
        const int r = idx >> 7, d = idx & 127;
        Qs[r * QSTR + d] = q[(qrow0 + r) * EDIM + h * DH + d] * scale;
    }

    float cumq[4];
    int srow[4];
#pragma unroll
    for (int i = 0; i < 4; i++) {
        srow[i] = qrow0 + ty * 4 + i;
        cumq[i] = g_cumS[h * S_LEN + srow[i]];
    }

    // per-thread K row bases + swizzle (rows 4tx+j)
    int kswz[4];
#pragma unroll
    for (int j = 0; j < 4; j++) {
        const int r = 4 * tx + j;
        kswz[j] = (r ^ (r >> 3)) & 7;
    }

    float m[4], l[4];
    ull o2[4][4];
#pragma unroll
    for (int i = 0; i < 4; i++) {
        m[i] = -INFINITY; l[i] = 0.f;
#pragma unroll
        for (int d = 0; d < 4; d++) o2[i][d] = 0ull;
    }

    cp_wait0();
    __syncthreads();

    for (int kt = 0; kt <= qi; kt++) {
        const int t0 = kt * BN;
        float* Kb = Ks0 + (kt & 1) * (64 * 128);
        float* Vb = Vs0 + (kt & 1) * (64 * VSTR);

        // gate inputs for this thread's 4 keys (hits L1/L2; issued early)
        const int c0 = tx * 4;
        const float4 igv  = *(const float4*)(g_ig   + h * S_LEN + t0 + c0);
        const float4 cumv = *(const float4*)(g_cumS + h * S_LEN + t0 + c0);
        float Bc[4] = {igv.x - cumv.x, igv.y - cumv.y,
                       igv.z - cumv.z, igv.w - cumv.w};

        // ---- QK^T 64x64x128, dot along k, packed pairs ----
        ull acc2[4][4];
#pragma unroll
        for (int i = 0; i < 4; i++)
#pragma unroll
            for (int j = 0; j < 4; j++) acc2[i][j] = 0ull;

#pragma unroll 8
        for (int ch = 0; ch < 32; ch++) {
            ulonglong2 qv[4], kv[4];
#pragma unroll
            for (int i = 0; i < 4; i++)
                qv[i] = *(const ulonglong2*)(Qs + (4 * ty + i) * QSTR + ch * 4);
#pragma unroll
            for (int j = 0; j < 4; j++)
                kv[j] = *(const ulonglong2*)(Kb + (4 * tx + j) * 128 + ((ch ^ kswz[j]) << 2));
#pragma unroll
            for (int i = 0; i < 4; i++)
#pragma unroll
                for (int j = 0; j < 4; j++) {
                    acc2[i][j] = ffma2(qv[i].x, kv[j].x, acc2[i][j]);
                    acc2[i][j] = ffma2(qv[i].y, kv[j].y, acc2[i][j]);
                }
        }
        float acc[4][4];
#pragma unroll
        for (int i = 0; i < 4; i++)
#pragma unroll
            for (int j = 0; j < 4; j++) {
                float lo, hi; unpk2(acc2[i][j], lo, hi);
                acc[i][j] = lo + hi;
            }

        // ---- gate math ----
        float P[4][4], fs[4], tl[4];
        if (kt < qi) {
            // full tile: single tile-wide B max, no masking
            float bmax = fmaxf(fmaxf(Bc[0], Bc[1]), fmaxf(Bc[2], Bc[3]));
#pragma unroll
            for (int off = 1; off < 16; off <<= 1)
                bmax = fmaxf(bmax, __shfl_xor_sync(0xffffffffu, bmax, off, 16));
            float eB[4];
#pragma unroll
            for (int j = 0; j < 4; j++) eB[j] = __expf(Bc[j] - bmax);
#pragma unroll
            for (int i = 0; i < 4; i++) {
                const float mn = fmaxf(m[i], cumq[i] + bmax);
                fs[i] = __expf(m[i] - mn);
                m[i] = mn;
                const float eA = __expf(cumq[i] - mn + bmax);
                float rs = 0.f;
#pragma unroll
                for (int j = 0; j < 4; j++) {
                    const float p = acc[i][j] * eA * eB[j];
                    P[i][j] = p;
                    rs += p;
                }
                tl[i] = rs;
            }
        } else {
            // diagonal tile: masked, per-element exp
            float rowB[4];
#pragma unroll
            for (int i = 0; i < 4; i++) {
                float rb = -INFINITY;
#pragma unroll
                for (int j = 0; j < 4; j++)
                    if (4 * tx + j <= 4 * ty + i) rb = fmaxf(rb, Bc[j]);
                rowB[i] = rb;
            }
#pragma unroll
            for (int i = 0; i < 4; i++) {
#pragma unroll
                for (int off = 1; off < 16; off <<= 1)
                    rowB[i] = fmaxf(rowB[i], __shfl_xor_sync(0xffffffffu, rowB[i], off, 16));
            }
#pragma unroll
            for (int i = 0; i < 4; i++) {
                const float mn = fmaxf(m[i], cumq[i] + rowB[i]);
                fs[i] = __expf(m[i] - mn);
                m[i] = mn;
                const float base = cumq[i] - mn;
                float rs = 0.f;
#pragma unroll
                for (int j = 0; j < 4; j++) {
                    const bool ok = (4 * tx + j <= 4 * ty + i);
                    const float p = ok ? acc[i][j] * __expf(base + Bc[j]) : 0.f;
                    P[i][j] = p;
                    rs += p;
                }
                tl[i] = rs;
            }
        }

#pragma unroll
        for (int i = 0; i < 4; i++) {
#pragma unroll
            for (int off = 1; off < 16; off <<= 1)
                tl[i] += __shfl_xor_sync(0xffffffffu, tl[i], off, 16);
            l[i] = l[i] * fs[i] + tl[i];
            const ull fsd = dup2f(fs[i]);
#pragma unroll
            for (int d = 0; d < 4; d++) o2[i][d] = fmul2(o2[i][d], fsd);
        }

        // stage P to smem: Ps[key][row]
#pragma unroll
        for (int j = 0; j < 4; j++) {
            float4 pv = make_float4(P[0][j], P[1][j], P[2][j], P[3][j]);
            *(float4*)(Ps + (c0 + j) * 68 + ty * 4) = pv;
        }
        __syncthreads();   // Ps visible to all

        if (kt < qi)
            prefetch_tile(kg0 + (size_t)(t0 + BN) * EDIM,
                          vg0 + (size_t)(t0 + BN) * EDIM,
                          Ks0 + ((kt + 1) & 1) * (64 * 128),
                          Vs0 + ((kt + 1) & 1) * (64 * VSTR), tid);

        // ---- P @ V (packed f32x2), dims 4tx..+3 and 64+4tx..+3 ----
#pragma unroll 8
        for (int tt = 0; tt < 64; tt++) {
            const float4 p4 = *(const float4*)(Ps + tt * 68 + ty * 4);
            const ulonglong2 va = *(const ulonglong2*)(Vb + tt * VSTR + tx * 4);
            const ulonglong2 vb = *(const ulonglong2*)(Vb + tt * VSTR + 64 + tx * 4);
            const float pa[4] = {p4.x, p4.y, p4.z, p4.w};
#pragma unroll
            for (int i = 0; i < 4; i++) {
                const ull pd = dup2f(pa[i]);
                o2[i][0] = ffma2(pd, va.x, o2[i][0]);
                o2[i][1] = ffma2(pd, va.y, o2[i][1]);
                o2[i][2] = ffma2(pd, vb.x, o2[i][2]);
                o2[i][3] = ffma2(pd, vb.y, o2[i][3]);
            }
        }

        if (kt < qi) cp_wait0();
        __syncthreads();   // next tile ready; PV done (Ps / buffers rotatable)
    }

    // epilogue: normalizer = max(|l|, exp(-m)); h = o / (norm + eps)
#pragma unroll
    for (int i = 0; i < 4; i++) {
        const float norm = fmaxf(fabsf(l[i]), __expf(-m[i])) + 1e-6f;
        const ull iv = dup2f(1.f / norm);
        float* dst = g_h + (size_t)srow[i] * EDIM + h * DH;
        ulonglong2 ra, rb;
        ra.x = fmul2(o2[i][0], iv); ra.y = fmul2(o2[i][1], iv);
        rb.x = fmul2(o2[i][2], iv); rb.y = fmul2(o2[i][3], iv);
        *(ulonglong2*)(dst + tx * 4)      = ra;
        *(ulonglong2*)(dst + 64 + tx * 4) = rb;
    }
}

// ---------------------------------------------------------------------------
// Kernel 4: residual layer norm.  out = LN(h) * (1 + w).
// ---------------------------------------------------------------------------
__global__ void ln_kernel(const float* __restrict__ lnw, float* __restrict__ out) {
    const int s = blockIdx.x;
    const int tid = threadIdx.x;
    const int lane = tid & 31, warp = tid >> 5;

    const float4 x = *(const float4*)(g_h + s * EDIM + tid * 4);

    __shared__ float wsum[8];
    __shared__ float stat[2];

    float lsum = x.x + x.y + x.z + x.w;
#pragma unroll
    for (int off = 16; off > 0; off >>= 1)
        lsum += __shfl_xor_sync(0xffffffffu, lsum, off);
    if (lane == 0) wsum[warp] = lsum;
    __syncthreads();
    if (tid == 0) {
        float t = 0.f;
#pragma unroll
        for (int w = 0; w < 8; w++) t += wsum[w];
        stat[0] = t * (1.f / 1024.f);
    }
    __syncthreads();
    const float mean = stat[0];

    const float d0 = x.x - mean, d1 = x.y - mean, d2 = x.z - mean, d3 = x.w - mean;
    float lsq = d0 * d0 + d1 * d1 + d2 * d2 + d3 * d3;
#pragma unroll
    for (int off = 16; off > 0; off >>= 1)
        lsq += __shfl_xor_sync(0xffffffffu, lsq, off);
    if (lane == 0) wsum[warp] = lsq;
    __syncthreads();
    if (tid == 0) {
        float t = 0.f;
#pragma unroll
        for (int w = 0; w < 8; w++) t += wsum[w];
        stat[1] = rsqrtf(t * (1.f / 1024.f) + 1e-5f);
    }
    __syncthreads();
    const float rstd = stat[1];

    const float4 w4 = *(const float4*)(lnw + tid * 4);
    float4 r;
    r.x = d0 * rstd * (1.f + w4.x);
    r.y = d1 * rstd * (1.f + w4.y);
    r.z = d2 * rstd * (1.f + w4.z);
    r.w = d3 * rstd * (1.f + w4.w);
    *(float4*)(out + s * EDIM + tid * 4) = r;
}

// ---------------------------------------------------------------------------
extern "C" void kernel_launch(void* const* d_in, const int* in_sizes, int n_in,
                              void* d_out, int out_size) {
    const float* q   = (const float*)d_in[0];
    const float* k   = (const float*)d_in[1];
    const float* v   = (const float*)d_in[2];
    const float* Wi  = (const float*)d_in[3];
    const float* bi  = (const float*)d_in[4];
    const float* Wf  = (const float*)d_in[5];
    const float* bf  = (const float*)d_in[6];
    const float* lnw = (const float*)d_in[7];
    float* out = (float*)d_out;

    gates_kernel<<<S_LEN / 4, 256>>>(q, k, v, Wi, bi, Wf, bf);
    scan_kernel<<<NH, 1024>>>();

    cudaFuncSetAttribute(mlstm_main_kernel,
                         cudaFuncAttributeMaxDynamicSharedMemorySize, SMEM_BYTES);
    mlstm_main_kernel<<<32 * NH, 256, SMEM_BYTES>>>(q, k, v);

    ln_kernel<<<S_LEN, 256>>>(lnw, out);
}